// round 1
// baseline (speedup 1.0000x reference)
#include <cuda_runtime.h>
#include <cstdint>

// ---------------------------------------------------------------------------
// RGCN2: 2-layer hetero GraphConv + BN/MLP head, fp32 throughout.
// Scratch: single __device__ global array (no allocations anywhere).
// ---------------------------------------------------------------------------

#define NNODES 50000
#define DFEAT 128

static const long long OFF_DEG   = 0;                       // 4*N floats (deg -> rsqrt scales)
static const long long OFF_STATS = 4LL * NNODES;            // 256 (col sums, sumsq)
static const long long OFF_BN    = OFF_STATS + 256;         // 256 (a, b)
static const long long SZ        = (long long)NNODES * DFEAT;
static const long long OFF_AGGA  = OFF_BN + 256;
static const long long OFF_AGGB  = OFF_AGGA + SZ;
static const long long OFF_HA    = OFF_AGGB + SZ;
static const long long OFF_HB    = OFF_HA + SZ;
static const long long OFF_H2A   = OFF_HB + SZ;
static const long long OFF_H2B   = OFF_H2A + SZ;
static const long long OFF_T     = OFF_H2B + SZ;
static const long long TOTAL     = OFF_T + SZ;              // 45,000,512 floats (~180 MB)

__device__ float g_mem[45000512];

// ---------------------------------------------------------------------------
// zero
// ---------------------------------------------------------------------------
__global__ void zero_kernel(long long off, long long n4) {
    long long i = (long long)blockIdx.x * blockDim.x + threadIdx.x;
    float4* p = reinterpret_cast<float4*>(g_mem + off);
    long long stride = (long long)gridDim.x * blockDim.x;
    float4 z = make_float4(0.f, 0.f, 0.f, 0.f);
    for (; i < n4; i += stride) p[i] = z;
}

// ---------------------------------------------------------------------------
// degree histogram (float counts; exact up to 2^24)
// ---------------------------------------------------------------------------
__global__ void degree_kernel(const int* __restrict__ src, const int* __restrict__ dst,
                              long long so, long long dofs, int E) {
    int e = blockIdx.x * blockDim.x + threadIdx.x;
    if (e < E) {
        atomicAdd(&g_mem[so + src[e]], 1.0f);
        atomicAdd(&g_mem[dofs + dst[e]], 1.0f);
    }
}

__global__ void rsqrt_kernel(long long off, int n) {
    int i = blockIdx.x * blockDim.x + threadIdx.x;
    if (i < n) {
        float v = g_mem[off + i];
        g_mem[off + i] = rsqrtf(fmaxf(v, 1.0f));
    }
}

// ---------------------------------------------------------------------------
// edge scatter: agg[dst] += x[src] * sOut[src]   (warp per edge, red.v4)
// ---------------------------------------------------------------------------
__global__ void scatter_kernel(const int* __restrict__ src, const int* __restrict__ dst,
                               const float* __restrict__ xg, long long x_off,
                               long long sout_off, long long agg_off, int E) {
    int e = (int)(((long long)blockIdx.x * blockDim.x + threadIdx.x) >> 5);
    int lane = threadIdx.x & 31;
    if (e >= E) return;
    const float* X = xg ? xg : (g_mem + x_off);
    int s = __ldg(src + e);
    int d = __ldg(dst + e);
    float sc = g_mem[sout_off + s];
    float4 v = *reinterpret_cast<const float4*>(X + (size_t)s * DFEAT + lane * 4);
    float* p = g_mem + agg_off + (size_t)d * DFEAT + lane * 4;
    asm volatile("red.global.add.v4.f32 [%0], {%1,%2,%3,%4};"
                 :: "l"(p), "f"(v.x * sc), "f"(v.y * sc), "f"(v.z * sc), "f"(v.w * sc)
                 : "memory");
}

// ---------------------------------------------------------------------------
// fused GEMM: Y[i,:] = act( scale[i] * (X[i,:] @ W) + bias )  (+= if ACCUM)
// X: [M,128] (g_mem), W: [128,128] row-major (d_in), Y: [M,128] (g_mem)
// BM=64, BN=128, BK=32; 128 threads; 8x8 register tile.
// Thread tx in [0,16): cols {tx*4..tx*4+3, 64+tx*4..64+tx*4+3}; ty in [0,8): rows ty*8..+7
// ---------------------------------------------------------------------------
template <bool SCALE, bool BIAS, bool RELU, bool ACCUM>
__global__ void __launch_bounds__(128) gemm_kernel(
    long long x_off, const float* __restrict__ W, const float* __restrict__ bias,
    long long scale_off, long long y_off, int M) {
    __shared__ float Xs[64][33];
    __shared__ float Ws[32][128];

    const float* X = g_mem + x_off;
    float* Y = g_mem + y_off;
    int tid = threadIdx.x;
    int tx = tid & 15;
    int ty = tid >> 4;
    int row0 = blockIdx.x * 64;

    float acc[8][8];
#pragma unroll
    for (int r = 0; r < 8; r++)
#pragma unroll
        for (int c = 0; c < 8; c++) acc[r][c] = 0.f;

    for (int kc = 0; kc < DFEAT; kc += 32) {
        // load X tile: 64x32 = 512 float4, 4 per thread
#pragma unroll
        for (int t = 0; t < 4; t++) {
            int idx = tid + t * 128;
            int r = idx >> 3, c4 = idx & 7;
            int gr = row0 + r;
            float4 v = make_float4(0.f, 0.f, 0.f, 0.f);
            if (gr < M) v = *reinterpret_cast<const float4*>(X + (size_t)gr * DFEAT + kc + c4 * 4);
            Xs[r][c4 * 4 + 0] = v.x;
            Xs[r][c4 * 4 + 1] = v.y;
            Xs[r][c4 * 4 + 2] = v.z;
            Xs[r][c4 * 4 + 3] = v.w;
        }
        // load W tile: 32x128 = 1024 float4, 8 per thread
#pragma unroll
        for (int t = 0; t < 8; t++) {
            int idx = tid + t * 128;
            int r = idx >> 5, c4 = idx & 31;
            float4 v = *reinterpret_cast<const float4*>(W + (size_t)(kc + r) * DFEAT + c4 * 4);
            *reinterpret_cast<float4*>(&Ws[r][c4 * 4]) = v;
        }
        __syncthreads();

#pragma unroll
        for (int kk = 0; kk < 32; kk++) {
            float a[8];
#pragma unroll
            for (int r = 0; r < 8; r++) a[r] = Xs[ty * 8 + r][kk];
            float4 b0 = *reinterpret_cast<const float4*>(&Ws[kk][tx * 4]);
            float4 b1 = *reinterpret_cast<const float4*>(&Ws[kk][64 + tx * 4]);
#pragma unroll
            for (int r = 0; r < 8; r++) {
                acc[r][0] = fmaf(a[r], b0.x, acc[r][0]);
                acc[r][1] = fmaf(a[r], b0.y, acc[r][1]);
                acc[r][2] = fmaf(a[r], b0.z, acc[r][2]);
                acc[r][3] = fmaf(a[r], b0.w, acc[r][3]);
                acc[r][4] = fmaf(a[r], b1.x, acc[r][4]);
                acc[r][5] = fmaf(a[r], b1.y, acc[r][5]);
                acc[r][6] = fmaf(a[r], b1.z, acc[r][6]);
                acc[r][7] = fmaf(a[r], b1.w, acc[r][7]);
            }
        }
        __syncthreads();
    }

    int colA = tx * 4, colB = 64 + tx * 4;
    float4 bA = make_float4(0.f, 0.f, 0.f, 0.f), bB = bA;
    if (BIAS) {
        bA = *reinterpret_cast<const float4*>(bias + colA);
        bB = *reinterpret_cast<const float4*>(bias + colB);
    }
#pragma unroll
    for (int r = 0; r < 8; r++) {
        int gr = row0 + ty * 8 + r;
        if (gr >= M) continue;
        float s = SCALE ? g_mem[scale_off + gr] : 1.0f;
        float4 o0, o1;
        o0.x = acc[r][0] * s + bA.x;
        o0.y = acc[r][1] * s + bA.y;
        o0.z = acc[r][2] * s + bA.z;
        o0.w = acc[r][3] * s + bA.w;
        o1.x = acc[r][4] * s + bB.x;
        o1.y = acc[r][5] * s + bB.y;
        o1.z = acc[r][6] * s + bB.z;
        o1.w = acc[r][7] * s + bB.w;
        if (ACCUM) {
            float4 p0 = *reinterpret_cast<const float4*>(Y + (size_t)gr * DFEAT + colA);
            float4 p1 = *reinterpret_cast<const float4*>(Y + (size_t)gr * DFEAT + colB);
            o0.x += p0.x; o0.y += p0.y; o0.z += p0.z; o0.w += p0.w;
            o1.x += p1.x; o1.y += p1.y; o1.z += p1.z; o1.w += p1.w;
        }
        if (RELU) {
            o0.x = fmaxf(o0.x, 0.f); o0.y = fmaxf(o0.y, 0.f);
            o0.z = fmaxf(o0.z, 0.f); o0.w = fmaxf(o0.w, 0.f);
            o1.x = fmaxf(o1.x, 0.f); o1.y = fmaxf(o1.y, 0.f);
            o1.z = fmaxf(o1.z, 0.f); o1.w = fmaxf(o1.w, 0.f);
        }
        *reinterpret_cast<float4*>(Y + (size_t)gr * DFEAT + colA) = o0;
        *reinterpret_cast<float4*>(Y + (size_t)gr * DFEAT + colB) = o1;
    }
}

// ---------------------------------------------------------------------------
// BN column stats: per-block partial sums over 128 rows, atomic into stats.
// ---------------------------------------------------------------------------
__global__ void bn_stats_kernel(long long t_off, int M) {
    int c = threadIdx.x;  // 128 threads = 128 columns
    int r0 = blockIdx.x * 128;
    int r1 = min(r0 + 128, M);
    const float* t = g_mem + t_off;
    float s = 0.f, s2 = 0.f;
    for (int i = r0; i < r1; i++) {
        float v = t[(size_t)i * DFEAT + c];
        s += v;
        s2 = fmaf(v, v, s2);
    }
    atomicAdd(&g_mem[OFF_STATS + c], s);
    atomicAdd(&g_mem[OFF_STATS + 128 + c], s2);
}

__global__ void bn_finalize_kernel(const float* __restrict__ gamma,
                                   const float* __restrict__ beta, int M) {
    int c = threadIdx.x;  // 128
    float inv_n = 1.0f / (float)M;
    float mu = g_mem[OFF_STATS + c] * inv_n;
    float var = g_mem[OFF_STATS + 128 + c] * inv_n - mu * mu;
    var = fmaxf(var, 0.f);
    float a = gamma[c] * rsqrtf(var + 1e-5f);
    g_mem[OFF_BN + c] = a;
    g_mem[OFF_BN + 128 + c] = beta[c] - mu * a;
}

// ---------------------------------------------------------------------------
// final: out[i,:2] = relu(t[i,:]*a + b) @ Wm2 ; warp per row
// ---------------------------------------------------------------------------
__global__ void final_kernel(const float* __restrict__ Wm2, float* __restrict__ out, int M) {
    int gw = (int)(((long long)blockIdx.x * blockDim.x + threadIdx.x) >> 5);
    int lane = threadIdx.x & 31;
    if (gw >= M) return;
    int c = lane * 4;
    const float* trow = g_mem + OFF_T + (size_t)gw * DFEAT;
    float4 tv = *reinterpret_cast<const float4*>(trow + c);
    float4 av = *reinterpret_cast<const float4*>(g_mem + OFF_BN + c);
    float4 bv = *reinterpret_cast<const float4*>(g_mem + OFF_BN + 128 + c);
    float4 w0 = *reinterpret_cast<const float4*>(Wm2 + c * 2);      // (c,0)(c,1)(c+1,0)(c+1,1)
    float4 w1 = *reinterpret_cast<const float4*>(Wm2 + c * 2 + 4);  // (c+2,..)(c+3,..)
    float v0 = fmaxf(fmaf(tv.x, av.x, bv.x), 0.f);
    float v1 = fmaxf(fmaf(tv.y, av.y, bv.y), 0.f);
    float v2 = fmaxf(fmaf(tv.z, av.z, bv.z), 0.f);
    float v3 = fmaxf(fmaf(tv.w, av.w, bv.w), 0.f);
    float acc0 = v0 * w0.x + v1 * w0.z + v2 * w1.x + v3 * w1.z;
    float acc1 = v0 * w0.y + v1 * w0.w + v2 * w1.y + v3 * w1.w;
#pragma unroll
    for (int o = 16; o; o >>= 1) {
        acc0 += __shfl_xor_sync(0xFFFFFFFFu, acc0, o);
        acc1 += __shfl_xor_sync(0xFFFFFFFFu, acc1, o);
    }
    if (lane == 0) {
        out[(size_t)gw * 2 + 0] = acc0;
        out[(size_t)gw * 2 + 1] = acc1;
    }
}

// ---------------------------------------------------------------------------
// host
// ---------------------------------------------------------------------------
extern "C" void kernel_launch(void* const* d_in, const int* in_sizes, int n_in,
                              void* d_out, int out_size) {
    const float* xA   = (const float*)d_in[0];
    const float* xB   = (const float*)d_in[1];
    const int*   src0 = (const int*)d_in[2];
    const int*   dst0 = (const int*)d_in[3];
    const int*   src1 = (const int*)d_in[4];
    const int*   dst1 = (const int*)d_in[5];
    const float* W1r0 = (const float*)d_in[6];
    const float* b1r0 = (const float*)d_in[7];
    const float* W1r1 = (const float*)d_in[8];
    const float* b1r1 = (const float*)d_in[9];
    const float* W2r0 = (const float*)d_in[10];
    const float* b2r0 = (const float*)d_in[11];
    const float* W2r1 = (const float*)d_in[12];
    const float* b2r1 = (const float*)d_in[13];
    const float* Wm1  = (const float*)d_in[14];
    const float* gamma= (const float*)d_in[15];
    const float* beta = (const float*)d_in[16];
    const float* Wm2  = (const float*)d_in[17];
    float* out = (float*)d_out;

    int M  = in_sizes[0] / DFEAT;   // 50000
    int E0 = in_sizes[2];           // 600000
    int E1 = in_sizes[4];

    long long sOut0 = OFF_DEG;                 // rsqrt out-deg r0 (A nodes)
    long long sIn0  = OFF_DEG + NNODES;        // rsqrt in-deg r0 (B nodes)
    long long sOut1 = OFF_DEG + 2LL * NNODES;  // rsqrt out-deg r1 (B nodes)
    long long sIn1  = OFF_DEG + 3LL * NNODES;  // rsqrt in-deg r1 (A nodes)

    // 1. zero degrees + stats + bn
    zero_kernel<<<256, 256>>>(OFF_DEG, (4LL * NNODES + 512) / 4);
    // 2-3. degree histograms
    degree_kernel<<<(E0 + 255) / 256, 256>>>(src0, dst0, sOut0, sIn0, E0);
    degree_kernel<<<(E1 + 255) / 256, 256>>>(src1, dst1, sOut1, sIn1, E1);
    // 4. deg -> rsqrt(max(deg,1))
    rsqrt_kernel<<<(4 * NNODES + 255) / 256, 256>>>(OFF_DEG, 4 * NNODES);

    int scat_grid0 = (int)(((long long)E0 * 32 + 255) / 256);
    int scat_grid1 = (int)(((long long)E1 * 32 + 255) / 256);
    int gemm_grid = (M + 63) / 64;

    // --- conv1 ---
    zero_kernel<<<4096, 256>>>(OFF_AGGA, 2 * SZ / 4);
    scatter_kernel<<<scat_grid0, 256>>>(src0, dst0, xA, 0, sOut0, OFF_AGGB, E0);
    scatter_kernel<<<scat_grid1, 256>>>(src1, dst1, xB, 0, sOut1, OFF_AGGA, E1);
    gemm_kernel<true, true, true, false><<<gemm_grid, 128>>>(OFF_AGGB, W1r0, b1r0, sIn0, OFF_HB, M);
    gemm_kernel<true, true, true, false><<<gemm_grid, 128>>>(OFF_AGGA, W1r1, b1r1, sIn1, OFF_HA, M);

    // --- conv2 ---
    zero_kernel<<<4096, 256>>>(OFF_AGGA, 2 * SZ / 4);
    scatter_kernel<<<scat_grid0, 256>>>(src0, dst0, nullptr, OFF_HA, sOut0, OFF_AGGB, E0);
    scatter_kernel<<<scat_grid1, 256>>>(src1, dst1, nullptr, OFF_HB, sOut1, OFF_AGGA, E1);
    gemm_kernel<true, true, false, false><<<gemm_grid, 128>>>(OFF_AGGB, W2r0, b2r0, sIn0, OFF_H2B, M);
    gemm_kernel<true, true, false, false><<<gemm_grid, 128>>>(OFF_AGGA, W2r1, b2r1, sIn1, OFF_H2A, M);

    // --- MLP: t = [h2A | h2B] @ Wm1 (split K=256 into two K=128 passes) ---
    gemm_kernel<false, false, false, false><<<gemm_grid, 128>>>(OFF_H2A, Wm1, nullptr, 0, OFF_T, M);
    gemm_kernel<false, false, false, true><<<gemm_grid, 128>>>(OFF_H2B, Wm1 + 128 * DFEAT, nullptr, 0, OFF_T, M);

    // --- BN + head ---
    bn_stats_kernel<<<(M + 127) / 128, 128>>>(OFF_T, M);
    bn_finalize_kernel<<<1, 128>>>(gamma, beta, M);
    final_kernel<<<(M + 7) / 8, 256>>>(Wm2, out, M);
}

// round 7
// speedup vs baseline: 1.1152x; 1.1152x over previous
#include <cuda_runtime.h>
#include <cuda_bf16.h>
#include <cstdint>

// ---------------------------------------------------------------------------
// RGCN2 on GB300 (sm_103): fp32 scatters + bf16-split HMMA (mma.sync) GEMMs
// + fused conv2+MLP weights. No tcgen05 (harness PTX target rejects it).
// ---------------------------------------------------------------------------

#define NNODES 50000
#define DFEAT 128

static const long long OFF_DEG   = 0;                        // 4*N rsqrt scales
static const long long OFF_STATS = 4LL * NNODES;             // 256
static const long long OFF_BN    = OFF_STATS + 256;          // 256
static const long long SZ        = (long long)NNODES * DFEAT;
static const long long OFF_AGGA  = OFF_BN + 256;
static const long long OFF_AGGB  = OFF_AGGA + SZ;
static const long long OFF_HA    = OFF_AGGB + SZ;
static const long long OFF_HB    = OFF_HA + SZ;
static const long long OFF_T     = OFF_HB + SZ;
static const long long OFF_WFA   = OFF_T + SZ;               // fused W (fp32 128x128)
static const long long OFF_WFB   = OFF_WFA + 16384;
static const long long OFF_BF    = OFF_WFB + 16384;          // fused bias (128)

__device__ float g_mem[32233472];

// ---------------------------------------------------------------------------
// utility kernels (unchanged from the passing R1 kernel)
// ---------------------------------------------------------------------------
__global__ void zero_kernel(long long off, long long n4) {
    long long i = (long long)blockIdx.x * blockDim.x + threadIdx.x;
    float4* p = reinterpret_cast<float4*>(g_mem + off);
    long long stride = (long long)gridDim.x * blockDim.x;
    float4 z = make_float4(0.f, 0.f, 0.f, 0.f);
    for (; i < n4; i += stride) p[i] = z;
}

__global__ void degree_kernel(const int* __restrict__ src, const int* __restrict__ dst,
                              long long so, long long dofs, int E) {
    int e = blockIdx.x * blockDim.x + threadIdx.x;
    if (e < E) {
        atomicAdd(&g_mem[so + src[e]], 1.0f);
        atomicAdd(&g_mem[dofs + dst[e]], 1.0f);
    }
}

__global__ void rsqrt_kernel(long long off, int n) {
    int i = blockIdx.x * blockDim.x + threadIdx.x;
    if (i < n) {
        float v = g_mem[off + i];
        g_mem[off + i] = rsqrtf(fmaxf(v, 1.0f));
    }
}

// agg[dst] += x[src] * sOut[src]   (warp per edge, red.global.v4)
__global__ void scatter_kernel(const int* __restrict__ src, const int* __restrict__ dst,
                               const float* __restrict__ xg, long long x_off,
                               long long sout_off, long long agg_off, int E) {
    int e = (int)(((long long)blockIdx.x * blockDim.x + threadIdx.x) >> 5);
    int lane = threadIdx.x & 31;
    if (e >= E) return;
    const float* X = xg ? xg : (g_mem + x_off);
    int s = __ldg(src + e);
    int d = __ldg(dst + e);
    float sc = g_mem[sout_off + s];
    float4 v = *reinterpret_cast<const float4*>(X + (size_t)s * DFEAT + lane * 4);
    float* p = g_mem + agg_off + (size_t)d * DFEAT + lane * 4;
    asm volatile("red.global.add.v4.f32 [%0], {%1,%2,%3,%4};"
                 :: "l"(p), "f"(v.x * sc), "f"(v.y * sc), "f"(v.z * sc), "f"(v.w * sc)
                 : "memory");
}

// Wf[k][j] = sum_t W2[k][t] * Wm1part[t][j]
__global__ void fuse_w_kernel(const float* __restrict__ W2, const float* __restrict__ Wm1p,
                              float* __restrict__ out) {
    int j = threadIdx.x;
    int k = blockIdx.x;
    float acc = 0.f;
#pragma unroll 4
    for (int t = 0; t < 128; t++)
        acc = fmaf(__ldg(W2 + k * 128 + t), __ldg(Wm1p + t * 128 + j), acc);
    out[k * 128 + j] = acc;
}

// bf[j] = sum_k b2r1[k]*Wm1[k][j] + b2r0[k]*Wm1[128+k][j]
__global__ void fuse_b_kernel(const float* __restrict__ b2r1, const float* __restrict__ b2r0,
                              const float* __restrict__ Wm1, float* __restrict__ bf) {
    int j = threadIdx.x;
    float acc = 0.f;
    for (int k = 0; k < 128; k++) {
        acc = fmaf(b2r1[k], Wm1[k * 128 + j], acc);
        acc = fmaf(b2r0[k], Wm1[(128 + k) * 128 + j], acc);
    }
    bf[j] = acc;
}

// ---------------------------------------------------------------------------
// mma.sync helpers (arch-agnostic PTX, works on plain sm_103 target)
// ---------------------------------------------------------------------------
__device__ __forceinline__ uint32_t smem_u32(const void* p) {
    uint32_t a;
    asm("{ .reg .u64 t; cvta.to.shared.u64 t, %1; cvt.u32.u64 %0, t; }" : "=r"(a) : "l"(p));
    return a;
}
__device__ __forceinline__ void ldsm_x4(uint32_t addr, uint32_t* r) {
    asm volatile("ldmatrix.sync.aligned.m8n8.x4.shared.b16 {%0,%1,%2,%3}, [%4];"
                 : "=r"(r[0]), "=r"(r[1]), "=r"(r[2]), "=r"(r[3]) : "r"(addr));
}
__device__ __forceinline__ void ldsm_x4_t(uint32_t addr, uint32_t* r) {
    asm volatile("ldmatrix.sync.aligned.m8n8.x4.trans.shared.b16 {%0,%1,%2,%3}, [%4];"
                 : "=r"(r[0]), "=r"(r[1]), "=r"(r[2]), "=r"(r[3]) : "r"(addr));
}
__device__ __forceinline__ void mma16816(float* d, const uint32_t* a, const uint32_t* b) {
    asm volatile(
        "mma.sync.aligned.m16n8k16.row.col.f32.bf16.bf16.f32 "
        "{%0,%1,%2,%3}, {%4,%5,%6,%7}, {%8,%9}, {%0,%1,%2,%3};"
        : "+f"(d[0]), "+f"(d[1]), "+f"(d[2]), "+f"(d[3])
        : "r"(a[0]), "r"(a[1]), "r"(a[2]), "r"(a[3]), "r"(b[0]), "r"(b[1]));
}

// ---------------------------------------------------------------------------
// HMMA GEMM with bf16 hi/lo split (3-pass compensation), fp32 in/out.
// Y[128 rows/CTA, 128] = sum_s relu?( (X_s * rowscale_s) @ W_s ) + bias
// smem: A_hi/A_lo [128][136] bf16, B_hi/B_lo [128][136] bf16 (k-major).
// 256 threads; warp tile 32x64 (2 m-tiles x 8 n-tiles of m16n8k16).
// ---------------------------------------------------------------------------
#define AS_STRIDE 136
#define SM_AH 0
#define SM_AL 34816
#define SM_BH 69632
#define SM_BL 104448
#define SMEM_BYTES 139264

template <bool RELU>
__global__ void __launch_bounds__(256) mma_gemm(
    const float* __restrict__ X0, const float* __restrict__ X1,
    const float* __restrict__ W0, const float* __restrict__ W1,
    const float* __restrict__ S0, const float* __restrict__ S1,
    const float* __restrict__ bias, float* __restrict__ Y,
    int M, int nsrc)
{
    extern __shared__ __align__(128) char smem[];
    uint32_t sb = smem_u32(smem);
    int tid = threadIdx.x;
    int wid = tid >> 5, lane = tid & 31;
    int row0 = blockIdx.x << 7;

    int wr = (wid & 3) * 32;   // warp row base in tile
    int wc = (wid >> 2) * 64;  // warp col base in tile

    float acc[2][8][4];
#pragma unroll
    for (int mi = 0; mi < 2; mi++)
#pragma unroll
        for (int ni = 0; ni < 8; ni++)
#pragma unroll
            for (int q = 0; q < 4; q++) acc[mi][ni][q] = 0.f;

    for (int s = 0; s < nsrc; s++) {
        if (s) __syncthreads();  // previous compute done before overwrite

        const float* X = s ? X1 : X0;
        const float* S = s ? S1 : S0;
        const float* W = s ? W1 : W0;

        // ---- A tile: 128x128 fp32 -> row-scaled -> bf16 hi/lo ----
        for (int idx = tid; idx < 128 * 32; idx += 256) {
            int r = idx >> 5, c4 = idx & 31;
            int gr = row0 + r;
            float4 v = make_float4(0.f, 0.f, 0.f, 0.f);
            float sc = 0.f;
            if (gr < M) {
                v = *reinterpret_cast<const float4*>(X + (size_t)gr * DFEAT + c4 * 4);
                sc = __ldg(S + gr);
            }
            v.x *= sc; v.y *= sc; v.z *= sc; v.w *= sc;
            __nv_bfloat16 hx = __float2bfloat16(v.x), hy = __float2bfloat16(v.y);
            __nv_bfloat16 hz = __float2bfloat16(v.z), hw = __float2bfloat16(v.w);
            __nv_bfloat16 lx = __float2bfloat16(v.x - __bfloat162float(hx));
            __nv_bfloat16 ly = __float2bfloat16(v.y - __bfloat162float(hy));
            __nv_bfloat16 lz = __float2bfloat16(v.z - __bfloat162float(hz));
            __nv_bfloat16 lw = __float2bfloat16(v.w - __bfloat162float(hw));
            uint32_t off = (uint32_t)(r * AS_STRIDE + c4 * 4) * 2;
            uint2 hv, lv;
            hv.x = ((uint32_t)__bfloat16_as_ushort(hy) << 16) | __bfloat16_as_ushort(hx);
            hv.y = ((uint32_t)__bfloat16_as_ushort(hw) << 16) | __bfloat16_as_ushort(hz);
            lv.x = ((uint32_t)__bfloat16_as_ushort(ly) << 16) | __bfloat16_as_ushort(lx);
            lv.y = ((uint32_t)__bfloat16_as_ushort(lw) << 16) | __bfloat16_as_ushort(lz);
            *reinterpret_cast<uint2*>(smem + SM_AH + off) = hv;
            *reinterpret_cast<uint2*>(smem + SM_AL + off) = lv;
        }
        // ---- B tile: W[k][n] row-major -> bf16 hi/lo (same layout) ----
        for (int idx = tid; idx < 128 * 32; idx += 256) {
            int k = idx >> 5, n4 = idx & 31;
            float4 w = *reinterpret_cast<const float4*>(W + (size_t)k * 128 + n4 * 4);
            __nv_bfloat16 hx = __float2bfloat16(w.x), hy = __float2bfloat16(w.y);
            __nv_bfloat16 hz = __float2bfloat16(w.z), hw = __float2bfloat16(w.w);
            __nv_bfloat16 lx = __float2bfloat16(w.x - __bfloat162float(hx));
            __nv_bfloat16 ly = __float2bfloat16(w.y - __bfloat162float(hy));
            __nv_bfloat16 lz = __float2bfloat16(w.z - __bfloat162float(hz));
            __nv_bfloat16 lw = __float2bfloat16(w.w - __bfloat162float(hw));
            uint32_t off = (uint32_t)(k * AS_STRIDE + n4 * 4) * 2;
            uint2 hv, lv;
            hv.x = ((uint32_t)__bfloat16_as_ushort(hy) << 16) | __bfloat16_as_ushort(hx);
            hv.y = ((uint32_t)__bfloat16_as_ushort(hw) << 16) | __bfloat16_as_ushort(hz);
            lv.x = ((uint32_t)__bfloat16_as_ushort(ly) << 16) | __bfloat16_as_ushort(lx);
            lv.y = ((uint32_t)__bfloat16_as_ushort(lw) << 16) | __bfloat16_as_ushort(lz);
            *reinterpret_cast<uint2*>(smem + SM_BH + off) = hv;
            *reinterpret_cast<uint2*>(smem + SM_BL + off) = lv;
        }
        __syncthreads();

        // ---- 3-pass compensated bf16 mma: hi*hi + hi*lo + lo*hi ----
#pragma unroll
        for (int p = 0; p < 3; p++) {
            uint32_t Aoff = sb + ((p == 2) ? SM_AL : SM_AH);
            uint32_t Boff = sb + ((p == 1) ? SM_BL : SM_BH);
            // per-thread ldmatrix address components
            uint32_t a_r = wr + (lane & 15);          // row within tile
            uint32_t a_c = (lane >> 4) * 8;           // k sub-offset
            uint32_t b_k = (lane & 15);               // k within step
            uint32_t b_c = (lane >> 4) * 8;           // n sub-offset
#pragma unroll
            for (int ks = 0; ks < 8; ks++) {
                int k0 = ks * 16;
                uint32_t a[2][4];
#pragma unroll
                for (int mi = 0; mi < 2; mi++) {
                    uint32_t addr = Aoff + ((a_r + mi * 16) * AS_STRIDE + k0 + a_c) * 2;
                    ldsm_x4(addr, a[mi]);
                }
                uint32_t b[4][4];  // [nj][ (ni0:b0,b1) (ni1:b0,b1) ]
#pragma unroll
                for (int nj = 0; nj < 4; nj++) {
                    uint32_t addr = Boff + ((k0 + b_k) * AS_STRIDE + wc + nj * 16 + b_c) * 2;
                    ldsm_x4_t(addr, b[nj]);
                }
#pragma unroll
                for (int mi = 0; mi < 2; mi++)
#pragma unroll
                    for (int nj = 0; nj < 4; nj++) {
                        mma16816(acc[mi][nj * 2 + 0], a[mi], &b[nj][0]);
                        mma16816(acc[mi][nj * 2 + 1], a[mi], &b[nj][2]);
                    }
            }
        }
    }

    // ---- epilogue: bias (+relu), fp32 stores ----
    int gi = lane >> 2, qi = lane & 3;
#pragma unroll
    for (int mi = 0; mi < 2; mi++) {
#pragma unroll
        for (int half = 0; half < 2; half++) {
            int gr = row0 + wr + mi * 16 + gi + half * 8;
            if (gr >= M) continue;
            float* Yr = Y + (size_t)gr * DFEAT;
#pragma unroll
            for (int ni = 0; ni < 8; ni++) {
                int c = wc + ni * 8 + qi * 2;
                float2 bv = *reinterpret_cast<const float2*>(bias + c);
                float2 o;
                o.x = acc[mi][ni][half * 2 + 0] + bv.x;
                o.y = acc[mi][ni][half * 2 + 1] + bv.y;
                if (RELU) { o.x = fmaxf(o.x, 0.f); o.y = fmaxf(o.y, 0.f); }
                *reinterpret_cast<float2*>(Yr + c) = o;
            }
        }
    }
}

// ---------------------------------------------------------------------------
// BN column stats + head
// ---------------------------------------------------------------------------
__global__ void bn_stats_kernel(long long t_off, int M) {
    int c = threadIdx.x;
    int r0 = blockIdx.x * 128;
    int r1 = min(r0 + 128, M);
    const float* t = g_mem + t_off;
    float s = 0.f, s2 = 0.f;
    for (int i = r0; i < r1; i++) {
        float v = t[(size_t)i * DFEAT + c];
        s += v;
        s2 = fmaf(v, v, s2);
    }
    atomicAdd(&g_mem[OFF_STATS + c], s);
    atomicAdd(&g_mem[OFF_STATS + 128 + c], s2);
}

__global__ void bn_finalize_kernel(const float* __restrict__ gamma,
                                   const float* __restrict__ beta, int M) {
    int c = threadIdx.x;
    float inv_n = 1.0f / (float)M;
    float mu = g_mem[OFF_STATS + c] * inv_n;
    float var = g_mem[OFF_STATS + 128 + c] * inv_n - mu * mu;
    var = fmaxf(var, 0.f);
    float a = gamma[c] * rsqrtf(var + 1e-5f);
    g_mem[OFF_BN + c] = a;
    g_mem[OFF_BN + 128 + c] = beta[c] - mu * a;
}

__global__ void final_kernel(const float* __restrict__ Wm2, float* __restrict__ out, int M) {
    int gw = (int)(((long long)blockIdx.x * blockDim.x + threadIdx.x) >> 5);
    int lane = threadIdx.x & 31;
    if (gw >= M) return;
    int c = lane * 4;
    const float* trow = g_mem + OFF_T + (size_t)gw * DFEAT;
    float4 tv = *reinterpret_cast<const float4*>(trow + c);
    float4 av = *reinterpret_cast<const float4*>(g_mem + OFF_BN + c);
    float4 bv = *reinterpret_cast<const float4*>(g_mem + OFF_BN + 128 + c);
    float4 w0 = *reinterpret_cast<const float4*>(Wm2 + c * 2);
    float4 w1 = *reinterpret_cast<const float4*>(Wm2 + c * 2 + 4);
    float v0 = fmaxf(fmaf(tv.x, av.x, bv.x), 0.f);
    float v1 = fmaxf(fmaf(tv.y, av.y, bv.y), 0.f);
    float v2 = fmaxf(fmaf(tv.z, av.z, bv.z), 0.f);
    float v3 = fmaxf(fmaf(tv.w, av.w, bv.w), 0.f);
    float acc0 = v0 * w0.x + v1 * w0.z + v2 * w1.x + v3 * w1.z;
    float acc1 = v0 * w0.y + v1 * w0.w + v2 * w1.y + v3 * w1.w;
#pragma unroll
    for (int o = 16; o; o >>= 1) {
        acc0 += __shfl_xor_sync(0xFFFFFFFFu, acc0, o);
        acc1 += __shfl_xor_sync(0xFFFFFFFFu, acc1, o);
    }
    if (lane == 0) {
        out[(size_t)gw * 2 + 0] = acc0;
        out[(size_t)gw * 2 + 1] = acc1;
    }
}

// ---------------------------------------------------------------------------
// host
// ---------------------------------------------------------------------------
extern "C" void kernel_launch(void* const* d_in, const int* in_sizes, int n_in,
                              void* d_out, int out_size) {
    const float* xA   = (const float*)d_in[0];
    const float* xB   = (const float*)d_in[1];
    const int*   src0 = (const int*)d_in[2];
    const int*   dst0 = (const int*)d_in[3];
    const int*   src1 = (const int*)d_in[4];
    const int*   dst1 = (const int*)d_in[5];
    const float* W1r0 = (const float*)d_in[6];
    const float* b1r0 = (const float*)d_in[7];
    const float* W1r1 = (const float*)d_in[8];
    const float* b1r1 = (const float*)d_in[9];
    const float* W2r0 = (const float*)d_in[10];
    const float* b2r0 = (const float*)d_in[11];
    const float* W2r1 = (const float*)d_in[12];
    const float* b2r1 = (const float*)d_in[13];
    const float* Wm1  = (const float*)d_in[14];
    const float* gamma= (const float*)d_in[15];
    const float* beta = (const float*)d_in[16];
    const float* Wm2  = (const float*)d_in[17];
    float* out = (float*)d_out;

    int M  = in_sizes[0] / DFEAT;
    int E0 = in_sizes[2];
    int E1 = in_sizes[4];

    float* gb = nullptr;
    cudaGetSymbolAddress((void**)&gb, g_mem);

    cudaFuncSetAttribute(mma_gemm<true>, cudaFuncAttributeMaxDynamicSharedMemorySize, SMEM_BYTES);
    cudaFuncSetAttribute(mma_gemm<false>, cudaFuncAttributeMaxDynamicSharedMemorySize, SMEM_BYTES);

    long long sOut0 = OFF_DEG;
    long long sIn0  = OFF_DEG + NNODES;
    long long sOut1 = OFF_DEG + 2LL * NNODES;
    long long sIn1  = OFF_DEG + 3LL * NNODES;

    // degrees + stats zero
    zero_kernel<<<256, 256>>>(OFF_DEG, (4LL * NNODES + 512) / 4);
    degree_kernel<<<(E0 + 255) / 256, 256>>>(src0, dst0, sOut0, sIn0, E0);
    degree_kernel<<<(E1 + 255) / 256, 256>>>(src1, dst1, sOut1, sIn1, E1);
    rsqrt_kernel<<<(4 * NNODES + 255) / 256, 256>>>(OFF_DEG, 4 * NNODES);

    // fused conv2+MLP weights (graph-independent)
    fuse_w_kernel<<<128, 128>>>(W2r1, Wm1, gb + OFF_WFA);
    fuse_w_kernel<<<128, 128>>>(W2r0, Wm1 + 128 * 128, gb + OFF_WFB);
    fuse_b_kernel<<<1, 128>>>(b2r1, b2r0, Wm1, gb + OFF_BF);

    int scat_grid0 = (int)(((long long)E0 * 32 + 255) / 256);
    int scat_grid1 = (int)(((long long)E1 * 32 + 255) / 256);
    int gemm_grid = (M + 127) / 128;

    // --- conv1 ---
    zero_kernel<<<4096, 256>>>(OFF_AGGA, 2 * SZ / 4);
    scatter_kernel<<<scat_grid0, 256>>>(src0, dst0, xA, 0, sOut0, OFF_AGGB, E0);
    scatter_kernel<<<scat_grid1, 256>>>(src1, dst1, xB, 0, sOut1, OFF_AGGA, E1);
    mma_gemm<true><<<gemm_grid, 256, SMEM_BYTES>>>(
        gb + OFF_AGGB, nullptr, W1r0, nullptr, gb + sIn0, nullptr, b1r0,
        gb + OFF_HB, M, 1);
    mma_gemm<true><<<gemm_grid, 256, SMEM_BYTES>>>(
        gb + OFF_AGGA, nullptr, W1r1, nullptr, gb + sIn1, nullptr, b1r1,
        gb + OFF_HA, M, 1);

    // --- conv2 scatters ---
    zero_kernel<<<4096, 256>>>(OFF_AGGA, 2 * SZ / 4);
    scatter_kernel<<<scat_grid0, 256>>>(src0, dst0, nullptr, OFF_HA, sOut0, OFF_AGGB, E0);
    scatter_kernel<<<scat_grid1, 256>>>(src1, dst1, nullptr, OFF_HB, sOut1, OFF_AGGA, E1);

    // --- fused conv2+MLP: t = (aggA*sIn1)@WfA + (aggB*sIn0)@WfB + bf ---
    mma_gemm<false><<<gemm_grid, 256, SMEM_BYTES>>>(
        gb + OFF_AGGA, gb + OFF_AGGB, gb + OFF_WFA, gb + OFF_WFB,
        gb + sIn1, gb + sIn0, gb + OFF_BF, gb + OFF_T, M, 2);

    // --- BN + head ---
    bn_stats_kernel<<<(M + 127) / 128, 128>>>(OFF_T, M);
    bn_finalize_kernel<<<1, 128>>>(gamma, beta, M);
    final_kernel<<<(M + 7) / 8, 256>>>(Wm2, out, M);
}